// round 9
// baseline (speedup 1.0000x reference)
#include <cuda_runtime.h>

// Problem constants: B=2, N=8192, T=32, C=64, K=16, NUM_BASES=4
#define Bv 2
#define Nv 8192
#define Tv 32
#define Cv 64
#define Kv 16
#define NB 4
#define TC4 (Tv * Cv / 4)   // 512 float4 per (b,n) row

// out[b,n,t,c] = tanh( sum_k z[b, nbr[n,k], t, c] * w[c,n,k] )
// w[c,n,k] = adj[n,k] * sum_base cc[c,base] * bw[base,n,k]
//
// 64 threads/CTA, thread = (c4 = tid&15, th = tid>>4), owns 8 output slots.
// R7: ascending-neighbor sweep (bitonic sort of (nbr<<4)|k), streaming stores.
// R9: prefetch.global.L2 prologue — all 16 neighbor rows (8 KB each) warmed
// into L2 right after the sort, overlapped with the weight-build latency, so
// the consuming LDGs see L2 hits instead of ~600-cyc DRAM misses. Attacks the
// latency x L1tex-queue-depth equilibrium identified in R6-R8.
__global__ __launch_bounds__(64, 10)
void geodcd_kernel(const float4* __restrict__ z4,
                   const int*    __restrict__ nbr,
                   const float*  __restrict__ adj,
                   const float*  __restrict__ bw,
                   const float*  __restrict__ cc,
                   float4*       __restrict__ out4)
{
    const int n   = blockIdx.x;
    const int b   = blockIdx.y;
    const int tid = threadIdx.x;   // 64 threads
    const int c4  = tid & 15;
    const int th  = tid >> 4;      // 0..3

    __shared__ float ws[Kv * Cv];     // [k][c] effective edge weights (4 KB)
    __shared__ float scc[NB * Cv];    // transposed channel coeffs [base][c]
    __shared__ float sbw[NB * Kv];    // basis weights for this n [base][k]
    __shared__ float sadj[Kv];

    // ---- cooperative, coalesced staging ----
    {
        const float4 ccv = reinterpret_cast<const float4*>(cc)[tid];
        scc[0 * Cv + tid] = ccv.x;   // transpose to [base][c]
        scc[1 * Cv + tid] = ccv.y;
        scc[2 * Cv + tid] = ccv.z;
        scc[3 * Cv + tid] = ccv.w;
    }
    sbw[tid] = bw[(size_t)th * (Nv * Kv) + n * Kv + c4];  // [base=th][k=c4]
    if (tid < Kv) sadj[tid] = adj[n * Kv + tid];

    // Neighbor index into lane register, packed with its k: (nbr<<4)|k.
    unsigned pk = ((unsigned)nbr[n * Kv + c4] << 4) | (unsigned)c4;

    // 16-element bitonic sort across lanes (lane&15); both half-warps hold
    // identical sorted sequences afterwards.
    #pragma unroll
    for (int size = 2; size <= 16; size <<= 1) {
        #pragma unroll
        for (int stride = size >> 1; stride > 0; stride >>= 1) {
            const unsigned q = __shfl_xor_sync(0xffffffffu, pk, stride);
            const bool dirUp = ((c4 & size) == 0);
            const bool lower = ((c4 & stride) == 0);
            pk = ((lower == dirUp) ? umin(pk, q) : umax(pk, q));
        }
    }

    const float4* zb = z4 + (size_t)b * Nv * TC4;

    // ---- R9: warm all 16 neighbor rows into L2 (fire-and-forget) ----
    // 64 threads x 128 B = 8 KB = one full row per prefetch step. Issued in
    // sorted order; overlaps with the weight-build latency below.
    #pragma unroll
    for (int i = 0; i < Kv; ++i) {
        const unsigned pp = __shfl_sync(0xffffffffu, pk, i);
        const char* ptr = reinterpret_cast<const char*>(zb + (size_t)(pp >> 4) * TC4)
                        + (size_t)tid * 128;
        asm volatile("prefetch.global.L2 [%0];" :: "l"(ptr));
    }

    __syncthreads();

    // ---- weight build: thread computes w[k][4*c4 .. 4*c4+3] for 4 k's ----
    {
        const float4 cb0 = reinterpret_cast<const float4*>(scc + 0 * Cv)[c4];
        const float4 cb1 = reinterpret_cast<const float4*>(scc + 1 * Cv)[c4];
        const float4 cb2 = reinterpret_cast<const float4*>(scc + 2 * Cv)[c4];
        const float4 cb3 = reinterpret_cast<const float4*>(scc + 3 * Cv)[c4];
        #pragma unroll
        for (int p = 0; p < 4; ++p) {
            const int k = th + 4 * p;
            const float a  = sadj[k];
            const float b0 = sbw[0 * Kv + k];
            const float b1 = sbw[1 * Kv + k];
            const float b2 = sbw[2 * Kv + k];
            const float b3 = sbw[3 * Kv + k];
            float4 w;
            w.x = a * (cb0.x * b0 + cb1.x * b1 + cb2.x * b2 + cb3.x * b3);
            w.y = a * (cb0.y * b0 + cb1.y * b1 + cb2.y * b2 + cb3.y * b3);
            w.z = a * (cb0.z * b0 + cb1.z * b1 + cb2.z * b2 + cb3.z * b3);
            w.w = a * (cb0.w * b0 + cb1.w * b1 + cb2.w * b2 + cb3.w * b3);
            reinterpret_cast<float4*>(ws)[k * (Cv / 4) + c4] = w;
        }
    }
    __syncthreads();

    // ---- gather + accumulate, neighbors in ascending index order ----
    float4* op = out4 + ((size_t)b * Nv + n) * TC4;
    const int sbase = c4 + 16 * th;   // slot for j=0; j-th slot = sbase + 64*j

    float4 acc[8];
    #pragma unroll
    for (int j = 0; j < 8; ++j) acc[j] = make_float4(0.f, 0.f, 0.f, 0.f);

    #pragma unroll
    for (int i = 0; i < Kv; ++i) {
        const unsigned p  = __shfl_sync(0xffffffffu, pk, i);  // sorted elem i
        const int nb = (int)(p >> 4);
        const int k  = (int)(p & 15u);
        const float4 w = reinterpret_cast<const float4*>(ws)[k * (Cv / 4) + c4];
        const float4* row = zb + (size_t)nb * TC4 + sbase;
        #pragma unroll
        for (int j = 0; j < 8; ++j) {
            const float4 zv = __ldg(row + 64 * j);
            acc[j].x = fmaf(zv.x, w.x, acc[j].x);
            acc[j].y = fmaf(zv.y, w.y, acc[j].y);
            acc[j].z = fmaf(zv.z, w.z, acc[j].z);
            acc[j].w = fmaf(zv.w, w.w, acc[j].w);
        }
    }

    #pragma unroll
    for (int j = 0; j < 8; ++j) {
        float4 r;
        r.x = tanhf(acc[j].x);
        r.y = tanhf(acc[j].y);
        r.z = tanhf(acc[j].z);
        r.w = tanhf(acc[j].w);
        __stcs(op + sbase + 64 * j, r);   // streaming store: don't pollute L2
    }
}

extern "C" void kernel_launch(void* const* d_in, const int* in_sizes, int n_in,
                              void* d_out, int out_size) {
    // metadata order: z, neighbor_indices, adjacency, basis_weights, channel_coeffs
    const float4* z4  = (const float4*)d_in[0];
    const int*    nbr = (const int*)   d_in[1];
    const float*  adj = (const float*) d_in[2];
    const float*  bw  = (const float*) d_in[3];
    const float*  cc  = (const float*) d_in[4];
    float4*       o4  = (float4*)      d_out;

    dim3 grid(Nv, Bv);   // b-major wave ordering keeps one batch's z L2-resident
    geodcd_kernel<<<grid, 64>>>(z4, nbr, adj, bw, cc, o4);
}

// round 10
// speedup vs baseline: 1.0409x; 1.0409x over previous
#include <cuda_runtime.h>
#include <cstdint>

// Problem constants: B=2, N=8192, T=32, C=64, K=16, NUM_BASES=4
#define Bv 2
#define Nv 8192
#define Tv 32
#define Cv 64
#define Kv 16
#define NB 4
#define TC4 (Tv * Cv / 4)      // 512 float4 per (b,n) row
#define ROW_BYTES 8192         // one (b,n) z row: 32*64*4 bytes
#define STAGES 8

// Dynamic SMEM layout (bytes):
#define SM_RING   0                         // 8 stages x 8192
#define SM_WS     (STAGES * ROW_BYTES)      // 65536: weights [k][c] 4KB
#define SM_SCC    (SM_WS + 4096)            // 69632: transposed cc [base][c] 1KB
#define SM_SBW    (SM_SCC + 1024)           // 70656: bw slice [base][k] 256B
#define SM_SADJ   (SM_SBW + 256)            // 70912: adj 64B
#define SM_MBAR   (SM_SADJ + 128)           // 71040: full[8], empty[8] (8B each)
#define SM_TOTAL  (SM_MBAR + 256)

__device__ __forceinline__ uint32_t smem_u32(const void* p) {
    uint32_t a;
    asm("{ .reg .u64 t; cvta.to.shared.u64 t, %1; cvt.u32.u64 %0, t; }"
        : "=r"(a) : "l"(p));
    return a;
}
#define MBAR_INIT(a, cnt) \
    asm volatile("mbarrier.init.shared.b64 [%0], %1;" :: "r"(a), "r"(cnt) : "memory")
#define MBAR_EXPECT_TX(a, bytes) \
    asm volatile("mbarrier.arrive.expect_tx.shared.b64 _, [%0], %1;" :: "r"(a), "r"(bytes) : "memory")
#define MBAR_ARRIVE(a) \
    asm volatile("mbarrier.arrive.shared.b64 _, [%0];" :: "r"(a) : "memory")
#define MBAR_WAIT(a, ph) do {                                                  \
    asm volatile(                                                              \
        "{\n\t.reg .pred P;\n\t"                                               \
        "WL_%=:\n\t"                                                           \
        "mbarrier.try_wait.parity.acquire.cta.shared::cta.b64 P, [%0], %1, 0x989680;\n\t" \
        "@P bra.uni WD_%=;\n\t"                                                \
        "bra.uni WL_%=;\n\t"                                                   \
        "WD_%=:\n\t}"                                                          \
        :: "r"(a), "r"(ph) : "memory");                                        \
} while (0)
#define TMA_BULK(dst, src, bytes, mbar) \
    asm volatile("cp.async.bulk.shared::cluster.global.mbarrier::complete_tx::bytes " \
                 "[%0], [%1], %2, [%3];" \
                 :: "r"(dst), "l"(src), "r"(bytes), "r"(mbar) : "memory")

// out[b,n,t,c] = tanh( sum_k z[b, nbr[n,k], t, c] * w[c,n,k] )
// w[c,n,k] = adj[n,k] * sum_base cc[c,base] * bw[base,n,k]
//
// R10: gather routed through TMA bulk copies (UBLKCP) into an 8-stage SMEM
// ring instead of LDG — the L2 request stream comes from the TMA engine and
// bypasses the per-SM L1tex wavefront queue that capped R5-R9 at ~70% LTS.
// 128 threads: tid0 produces (sorted row order, R7), all threads consume from
// SMEM (LDS, no miss latency) and FMA into registers. Streaming stores out.
__global__ __launch_bounds__(128)
void geodcd_kernel(const float*  __restrict__ zf,
                   const int*    __restrict__ nbr,
                   const float*  __restrict__ adj,
                   const float*  __restrict__ bw,
                   const float*  __restrict__ cc,
                   float4*       __restrict__ out4)
{
    extern __shared__ char smem[];
    const uint32_t smb = smem_u32(smem);

    const int n   = blockIdx.x;
    const int b   = blockIdx.y;
    const int tid = threadIdx.x;   // 128 threads
    const int c4  = tid & 15;
    const int th  = tid >> 4;      // 0..7

    float* ring = reinterpret_cast<float*>(smem + SM_RING);
    float* ws   = reinterpret_cast<float*>(smem + SM_WS);
    float* scc  = reinterpret_cast<float*>(smem + SM_SCC);
    float* sbw  = reinterpret_cast<float*>(smem + SM_SBW);
    float* sadj = reinterpret_cast<float*>(smem + SM_SADJ);
    const uint32_t mb_full  = smb + SM_MBAR;          // 8 x 8B
    const uint32_t mb_empty = smb + SM_MBAR + 64;     // 8 x 8B

    // ---- cooperative, coalesced staging ----
    if (tid < Cv) {
        const float4 ccv = reinterpret_cast<const float4*>(cc)[tid];
        scc[0 * Cv + tid] = ccv.x;   // transpose to [base][c]
        scc[1 * Cv + tid] = ccv.y;
        scc[2 * Cv + tid] = ccv.z;
        scc[3 * Cv + tid] = ccv.w;
    }
    if (tid < NB * Kv)
        sbw[tid] = bw[(size_t)(tid >> 4) * (Nv * Kv) + n * Kv + (tid & 15)];
    if (tid < Kv) sadj[tid] = adj[n * Kv + tid];

    // Neighbor index packed with its k: (nbr<<4)|k; bitonic sort over lane&15
    // so every warp holds the identical ascending sequence.
    unsigned pk = ((unsigned)nbr[n * Kv + c4] << 4) | (unsigned)c4;
    #pragma unroll
    for (int size = 2; size <= 16; size <<= 1) {
        #pragma unroll
        for (int stride = size >> 1; stride > 0; stride >>= 1) {
            const unsigned q = __shfl_xor_sync(0xffffffffu, pk, stride);
            const bool dirUp = ((c4 & size) == 0);
            const bool lower = ((c4 & stride) == 0);
            pk = ((lower == dirUp) ? umin(pk, q) : umax(pk, q));
        }
    }
    unsigned p[Kv];
    #pragma unroll
    for (int i = 0; i < Kv; ++i)
        p[i] = __shfl_sync(0xffffffffu, pk, i);

    // ---- mbarrier init ----
    if (tid == 0) {
        #pragma unroll
        for (int s = 0; s < STAGES; ++s) {
            MBAR_INIT(mb_full  + s * 8, 1);     // completes via expect_tx
            MBAR_INIT(mb_empty + s * 8, 128);   // all threads arrive
        }
    }
    __syncthreads();

    const float* zb = zf + (size_t)b * Nv * (Tv * Cv);

    // ---- producer prologue: fill all 8 stages (sorted order) ----
    if (tid == 0) {
        #pragma unroll
        for (int i = 0; i < STAGES; ++i) {
            const uint32_t mb = mb_full + i * 8;
            MBAR_EXPECT_TX(mb, ROW_BYTES);
            const float* src = zb + (size_t)(p[i] >> 4) * (Tv * Cv);
            TMA_BULK(smb + SM_RING + i * ROW_BYTES, src, ROW_BYTES, mb);
        }
    }

    // ---- weight build (overlaps with TMA fills): threads 0..63 ----
    if (tid < 64) {
        const int bc4 = tid & 15;
        const int bth = tid >> 4;   // 0..3
        const float4 cb0 = reinterpret_cast<const float4*>(scc + 0 * Cv)[bc4];
        const float4 cb1 = reinterpret_cast<const float4*>(scc + 1 * Cv)[bc4];
        const float4 cb2 = reinterpret_cast<const float4*>(scc + 2 * Cv)[bc4];
        const float4 cb3 = reinterpret_cast<const float4*>(scc + 3 * Cv)[bc4];
        #pragma unroll
        for (int q = 0; q < 4; ++q) {
            const int k = bth + 4 * q;
            const float a  = sadj[k];
            const float b0 = sbw[0 * Kv + k];
            const float b1 = sbw[1 * Kv + k];
            const float b2 = sbw[2 * Kv + k];
            const float b3 = sbw[3 * Kv + k];
            float4 w;
            w.x = a * (cb0.x * b0 + cb1.x * b1 + cb2.x * b2 + cb3.x * b3);
            w.y = a * (cb0.y * b0 + cb1.y * b1 + cb2.y * b2 + cb3.y * b3);
            w.z = a * (cb0.z * b0 + cb1.z * b1 + cb2.z * b2 + cb3.z * b3);
            w.w = a * (cb0.w * b0 + cb1.w * b1 + cb2.w * b2 + cb3.w * b3);
            reinterpret_cast<float4*>(ws)[k * (Cv / 4) + bc4] = w;
        }
    }
    __syncthreads();

    // ---- consume ring; reissue row i+8 into drained stage ----
    const int sbase = c4 + 16 * th;   // float4 slot; j-th slot = sbase + 128*j

    float4 acc0 = make_float4(0.f, 0.f, 0.f, 0.f);
    float4 acc1 = make_float4(0.f, 0.f, 0.f, 0.f);
    float4 acc2 = make_float4(0.f, 0.f, 0.f, 0.f);
    float4 acc3 = make_float4(0.f, 0.f, 0.f, 0.f);

    #pragma unroll
    for (int i = 0; i < Kv; ++i) {
        const int slot = i & (STAGES - 1);
        MBAR_WAIT(mb_full + slot * 8, (i >> 3));   // parity: pass 0 / pass 1

        const int k = (int)(p[i] & 15u);
        const float4 w = reinterpret_cast<const float4*>(ws)[k * (Cv / 4) + c4];
        const float4* row = reinterpret_cast<const float4*>(ring) + slot * (ROW_BYTES / 16);
        const float4 z0 = row[sbase];
        const float4 z1 = row[sbase + 128];
        const float4 z2 = row[sbase + 256];
        const float4 z3 = row[sbase + 384];
        acc0.x = fmaf(z0.x, w.x, acc0.x);
        acc0.y = fmaf(z0.y, w.y, acc0.y);
        acc0.z = fmaf(z0.z, w.z, acc0.z);
        acc0.w = fmaf(z0.w, w.w, acc0.w);
        acc1.x = fmaf(z1.x, w.x, acc1.x);
        acc1.y = fmaf(z1.y, w.y, acc1.y);
        acc1.z = fmaf(z1.z, w.z, acc1.z);
        acc1.w = fmaf(z1.w, w.w, acc1.w);
        acc2.x = fmaf(z2.x, w.x, acc2.x);
        acc2.y = fmaf(z2.y, w.y, acc2.y);
        acc2.z = fmaf(z2.z, w.z, acc2.z);
        acc2.w = fmaf(z2.w, w.w, acc2.w);
        acc3.x = fmaf(z3.x, w.x, acc3.x);
        acc3.y = fmaf(z3.y, w.y, acc3.y);
        acc3.z = fmaf(z3.z, w.z, acc3.z);
        acc3.w = fmaf(z3.w, w.w, acc3.w);

        MBAR_ARRIVE(mb_empty + slot * 8);

        // Producer refills this stage with row i+8 once it drains.
        if (i + STAGES < Kv && tid == 0) {
            MBAR_WAIT(mb_empty + slot * 8, 0);   // first (only) completion
            const uint32_t mb = mb_full + slot * 8;
            MBAR_EXPECT_TX(mb, ROW_BYTES);
            const float* src = zb + (size_t)(p[i + STAGES] >> 4) * (Tv * Cv);
            TMA_BULK(smb + SM_RING + slot * ROW_BYTES, src, ROW_BYTES, mb);
        }
    }

    // ---- epilogue ----
    float4* op = out4 + ((size_t)b * Nv + n) * TC4;
    float4 r0, r1, r2, r3;
    r0.x = tanhf(acc0.x); r0.y = tanhf(acc0.y); r0.z = tanhf(acc0.z); r0.w = tanhf(acc0.w);
    r1.x = tanhf(acc1.x); r1.y = tanhf(acc1.y); r1.z = tanhf(acc1.z); r1.w = tanhf(acc1.w);
    r2.x = tanhf(acc2.x); r2.y = tanhf(acc2.y); r2.z = tanhf(acc2.z); r2.w = tanhf(acc2.w);
    r3.x = tanhf(acc3.x); r3.y = tanhf(acc3.y); r3.z = tanhf(acc3.z); r3.w = tanhf(acc3.w);
    __stcs(op + sbase,       r0);
    __stcs(op + sbase + 128, r1);
    __stcs(op + sbase + 256, r2);
    __stcs(op + sbase + 384, r3);
}

extern "C" void kernel_launch(void* const* d_in, const int* in_sizes, int n_in,
                              void* d_out, int out_size) {
    // metadata order: z, neighbor_indices, adjacency, basis_weights, channel_coeffs
    const float* zf  = (const float*)d_in[0];
    const int*   nbr = (const int*)  d_in[1];
    const float* adj = (const float*)d_in[2];
    const float* bw  = (const float*)d_in[3];
    const float* cc  = (const float*)d_in[4];
    float4*      o4  = (float4*)     d_out;

    static bool attr_set = false;
    if (!attr_set) {
        cudaFuncSetAttribute(geodcd_kernel,
                             cudaFuncAttributeMaxDynamicSharedMemorySize, SM_TOTAL);
        attr_set = true;
    }

    dim3 grid(Nv, Bv);   // b-major wave ordering keeps one batch's z L2-resident
    geodcd_kernel<<<grid, 128, SM_TOTAL>>>(zf, nbr, adj, bw, cc, o4);
}